// round 4
// baseline (speedup 1.0000x reference)
#include <cuda_runtime.h>
#include <cuda_bf16.h>

// B=8192, L=1, K=32, H=1024. TWO batches per CTA (grid 4096, 256 thr).
// Amortizes the per-CTA serial epilogue (reduction drain + MLP + barriers)
// over 256KB of streamed hiddens instead of 128KB, and halves wave count.
// Scalar tail is parallelized across the two batches (warp0/warp1, 128 MLP thr).

#define KK 32
#define HH 1024

__global__ __launch_bounds__(256, 6) void mu_kernel(
    const int*   __restrict__ vals,
    const float* __restrict__ distances,
    const float* __restrict__ cache_hidden,
    const float* __restrict__ hiddens,
    const float* __restrict__ W1,
    const float* __restrict__ b1,
    const float* __restrict__ W2,
    const float* __restrict__ b2,
    float* __restrict__ out, int N)
{
    __shared__ float4 sc4[2][HH / 4];              // cache rows (8 KB)
    __shared__ __align__(16) float sx[2][96];      // [cd | dist | counts] x2
    __shared__ float shid[2][64];

    const int b0   = blockIdx.x * 2;
    const int tid  = threadIdx.x;
    const int warp = tid >> 5;
    const int lane = tid & 31;

    // stage both cache_hidden rows (256 float4 each)
    sc4[0][tid] = ((const float4*)(cache_hidden + (size_t)b0 * HH))[tid];
    sc4[1][tid] = ((const float4*)(cache_hidden + (size_t)(b0 + 1) * HH))[tid];

    // warps 0/1: distances + distinct-nonzero prefix counts for batch 0/1
    if (warp < 2) {
        const int bb = b0 + warp;
        sx[warp][32 + lane] = distances[bb * KK + lane];
        int v = vals[bb * KK + lane];
        unsigned m = __match_any_sync(0xffffffffu, v);
        int isnew = (v != 0) && ((m & ((1u << lane) - 1u)) == 0);
        int cnt = isnew;
        #pragma unroll
        for (int o = 1; o < 32; o <<= 1) {
            int t = __shfl_up_sync(0xffffffffu, cnt, o);
            if (lane >= o) cnt += t;
        }
        sx[warp][64 + lane] = (float)cnt;
    }
    __syncthreads();

    // --- cdist: 4 interleaved k-streams per warp, 2 batches sequentially ---
    const int kbase = warp * 4;
    #pragma unroll
    for (int j = 0; j < 2; j++) {
        const float4* H4 = (const float4*)(hiddens + (size_t)(b0 + j) * KK * HH);
        const float4* r0 = &H4[(kbase + 0) * 256];
        const float4* r1 = &H4[(kbase + 1) * 256];
        const float4* r2 = &H4[(kbase + 2) * 256];
        const float4* r3 = &H4[(kbase + 3) * 256];
        const float4* cs = sc4[j];

        float a0 = 0.f, a1 = 0.f, a2 = 0.f, a3 = 0.f;
        #pragma unroll
        for (int it = 0; it < 8; it++) {
            int idx = it * 32 + lane;                  // coalesced 512B per LDG
            float4 c  = cs[idx];
            float4 x0 = __ldcs(&r0[idx]);
            float4 x1 = __ldcs(&r1[idx]);
            float4 x2 = __ldcs(&r2[idx]);
            float4 x3 = __ldcs(&r3[idx]);
            float d;
            d = c.x - x0.x; a0 += d * d;  d = c.y - x0.y; a0 += d * d;
            d = c.z - x0.z; a0 += d * d;  d = c.w - x0.w; a0 += d * d;
            d = c.x - x1.x; a1 += d * d;  d = c.y - x1.y; a1 += d * d;
            d = c.z - x1.z; a1 += d * d;  d = c.w - x1.w; a1 += d * d;
            d = c.x - x2.x; a2 += d * d;  d = c.y - x2.y; a2 += d * d;
            d = c.z - x2.z; a2 += d * d;  d = c.w - x2.w; a2 += d * d;
            d = c.x - x3.x; a3 += d * d;  d = c.y - x3.y; a3 += d * d;
            d = c.z - x3.z; a3 += d * d;  d = c.w - x3.w; a3 += d * d;
        }
        #pragma unroll
        for (int o = 16; o; o >>= 1) {
            a0 += __shfl_xor_sync(0xffffffffu, a0, o);
            a1 += __shfl_xor_sync(0xffffffffu, a1, o);
            a2 += __shfl_xor_sync(0xffffffffu, a2, o);
            a3 += __shfl_xor_sync(0xffffffffu, a3, o);
        }
        if (lane == 0) {
            sx[j][kbase + 0] = sqrtf(a0);
            sx[j][kbase + 1] = sqrtf(a1);
            sx[j][kbase + 2] = sqrtf(a2);
            sx[j][kbase + 3] = sqrtf(a3);
        }
    }
    __syncthreads();

    // --- MLP layer 1: 128 threads = 64 neurons x 2 batches ---
    if (tid < 128) {
        const int j = tid >> 6;          // batch
        const int n = tid & 63;          // neuron
        const float4* w4 = (const float4*)(W1 + n * 96);
        const float4* x4 = (const float4*)sx[j];
        float acc = __ldg(&b1[n]);
        #pragma unroll
        for (int i = 0; i < 24; i++) {
            float4 w = __ldg(&w4[i]);
            float4 x = x4[i];
            acc += w.x * x.x + w.y * x.y + w.z * x.z + w.w * x.w;
        }
        shid[j][n] = tanhf(acc);
    }
    __syncthreads();

    // --- layer 2 + sigmoid + scale + write: warp j handles batch j ---
    if (warp < 2) {
        const int j = warp;
        float s = shid[j][lane] * __ldg(&W2[lane])
                + shid[j][lane + 32] * __ldg(&W2[lane + 32]);
        #pragma unroll
        for (int o = 16; o; o >>= 1) s += __shfl_xor_sync(0xffffffffu, s, o);
        s += __ldg(&b2[0]);
        float mu = 1.f / (1.f + expf(-s));
        float scale = __shfl_sync(0xffffffffu, 5.f * mu, 0);
        float cd = sx[j][lane] * scale;
        int o0 = (b0 + j) * KK + lane;
        out[o0]     = cd;
        out[N + o0] = sx[j][32 + lane] + cd;
    }
}

extern "C" void kernel_launch(void* const* d_in, const int* in_sizes, int n_in,
                              void* d_out, int out_size)
{
    const int*   vals         = (const int*)  d_in[0];
    const float* distances    = (const float*)d_in[1];
    const float* cache_hidden = (const float*)d_in[2];
    const float* hiddens      = (const float*)d_in[3];
    const float* W1           = (const float*)d_in[4];
    const float* b1           = (const float*)d_in[5];
    const float* W2           = (const float*)d_in[6];
    const float* b2           = (const float*)d_in[7];
    float* out = (float*)d_out;

    int N = in_sizes[1];              // B*L*K = 262144
    int B = N / KK;                   // 8192

    mu_kernel<<<B / 2, 256>>>(vals, distances, cache_hidden, hiddens,
                              W1, b1, W2, b2, out, N);
}

// round 5
// speedup vs baseline: 1.2587x; 1.2587x over previous
#include <cuda_runtime.h>
#include <cuda_bf16.h>

// B=8192, L=1, K=32, H=1024. One CTA per batch row (grid 8192, 256 thr).
// R2 structure (4 interleaved k-streams per warp) + launch_bounds(256,8)
// to force regs<=32 -> 8 CTAs/SM, ~100% occupancy, more loads in flight.

#define KK 32
#define HH 1024

__global__ __launch_bounds__(256, 8) void mu_kernel(
    const int*   __restrict__ vals,
    const float* __restrict__ distances,
    const float* __restrict__ cache_hidden,
    const float* __restrict__ hiddens,
    const float* __restrict__ W1,
    const float* __restrict__ b1,
    const float* __restrict__ W2,
    const float* __restrict__ b2,
    float* __restrict__ out, int N)
{
    __shared__ float4 sc4[HH / 4];                 // cache_hidden row (4 KB)
    __shared__ __align__(16) float sx[96];         // [cd | dist | label_counts]
    __shared__ float shid[64];

    const int b    = blockIdx.x;
    const int tid  = threadIdx.x;
    const int warp = tid >> 5;
    const int lane = tid & 31;

    // stage cache_hidden[b] (1024 f32 = 256 float4, one per thread)
    sc4[tid] = ((const float4*)(cache_hidden + (size_t)b * HH))[tid];
    __syncthreads();

    // --- cdist: 4 interleaved k-streams per warp ---
    // single base pointer; row offsets are compile-time immediates (256,512,768)
    const float4* Hbase = (const float4*)(hiddens + (size_t)b * KK * HH)
                        + (size_t)warp * 4 * 256;

    float a0 = 0.f, a1 = 0.f, a2 = 0.f, a3 = 0.f;
    #pragma unroll
    for (int it = 0; it < 8; it++) {
        int idx = it * 32 + lane;                  // coalesced 512B per LDG
        float4 c  = sc4[idx];
        float4 x0 = __ldcs(Hbase + idx);
        float4 x1 = __ldcs(Hbase + 256 + idx);
        float4 x2 = __ldcs(Hbase + 512 + idx);
        float4 x3 = __ldcs(Hbase + 768 + idx);
        float d;
        d = c.x - x0.x; a0 += d * d;  d = c.y - x0.y; a0 += d * d;
        d = c.z - x0.z; a0 += d * d;  d = c.w - x0.w; a0 += d * d;
        d = c.x - x1.x; a1 += d * d;  d = c.y - x1.y; a1 += d * d;
        d = c.z - x1.z; a1 += d * d;  d = c.w - x1.w; a1 += d * d;
        d = c.x - x2.x; a2 += d * d;  d = c.y - x2.y; a2 += d * d;
        d = c.z - x2.z; a2 += d * d;  d = c.w - x2.w; a2 += d * d;
        d = c.x - x3.x; a3 += d * d;  d = c.y - x3.y; a3 += d * d;
        d = c.z - x3.z; a3 += d * d;  d = c.w - x3.w; a3 += d * d;
    }
    #pragma unroll
    for (int o = 16; o; o >>= 1) {
        a0 += __shfl_xor_sync(0xffffffffu, a0, o);
        a1 += __shfl_xor_sync(0xffffffffu, a1, o);
        a2 += __shfl_xor_sync(0xffffffffu, a2, o);
        a3 += __shfl_xor_sync(0xffffffffu, a3, o);
    }
    if (lane == 0) {
        const int kbase = warp * 4;
        sx[kbase + 0] = sqrtf(a0);
        sx[kbase + 1] = sqrtf(a1);
        sx[kbase + 2] = sqrtf(a2);
        sx[kbase + 3] = sqrtf(a3);
    }

    // --- warp 0: distances + distinct-nonzero prefix counts ---
    if (warp == 0) {
        sx[32 + lane] = distances[b * KK + lane];
        int v = vals[b * KK + lane];
        unsigned m = __match_any_sync(0xffffffffu, v);
        int isnew = (v != 0) && ((m & ((1u << lane) - 1u)) == 0);
        int cnt = isnew;
        #pragma unroll
        for (int o = 1; o < 32; o <<= 1) {
            int t = __shfl_up_sync(0xffffffffu, cnt, o);
            if (lane >= o) cnt += t;
        }
        sx[64 + lane] = (float)cnt;
    }
    __syncthreads();

    // --- MLP layer 1: 64 threads, W1 straight from gmem (L1-resident) ---
    if (tid < 64) {
        const float4* w4 = (const float4*)(W1 + tid * 96);
        const float4* x4 = (const float4*)sx;
        float acc = __ldg(&b1[tid]);
        #pragma unroll
        for (int i = 0; i < 24; i++) {
            float4 w = __ldg(&w4[i]);
            float4 x = x4[i];
            acc += w.x * x.x + w.y * x.y + w.z * x.z + w.w * x.w;
        }
        shid[tid] = tanhf(acc);
    }
    __syncthreads();

    // --- warp 0: layer 2 + sigmoid + scale + write ---
    if (warp == 0) {
        float s = shid[lane] * __ldg(&W2[lane])
                + shid[lane + 32] * __ldg(&W2[lane + 32]);
        #pragma unroll
        for (int o = 16; o; o >>= 1) s += __shfl_xor_sync(0xffffffffu, s, o);
        s += __ldg(&b2[0]);
        float mu = 1.f / (1.f + expf(-s));
        float scale = __shfl_sync(0xffffffffu, 5.f * mu, 0);
        float cd = sx[lane] * scale;
        int o0 = b * KK + lane;
        out[o0]     = cd;
        out[N + o0] = sx[32 + lane] + cd;
    }
}

extern "C" void kernel_launch(void* const* d_in, const int* in_sizes, int n_in,
                              void* d_out, int out_size)
{
    const int*   vals         = (const int*)  d_in[0];
    const float* distances    = (const float*)d_in[1];
    const float* cache_hidden = (const float*)d_in[2];
    const float* hiddens      = (const float*)d_in[3];
    const float* W1           = (const float*)d_in[4];
    const float* b1           = (const float*)d_in[5];
    const float* W2           = (const float*)d_in[6];
    const float* b2           = (const float*)d_in[7];
    float* out = (float*)d_out;

    int N = in_sizes[1];              // B*L*K = 262144
    int B = N / KK;                   // 8192

    mu_kernel<<<B, 256>>>(vals, distances, cache_hidden, hiddens,
                          W1, b1, W2, b2, out, N);
}